// round 3
// baseline (speedup 1.0000x reference)
#include <cuda_runtime.h>
#include <math.h>

#define NTHREADS 1024

// Bitwise-match jnp.nan_to_num: NaN -> 0, +inf -> FLT_MAX, -inf -> -FLT_MAX
__device__ __forceinline__ float nan_to_num_f(float x) {
    if (isnan(x)) return 0.0f;
    return fminf(fmaxf(x, -3.402823466385288598e38f), 3.402823466385288598e38f);
}

__global__ __launch_bounds__(NTHREADS, 1)
void sampler_kernel(const float* __restrict__ logits,
                    const float* __restrict__ temps,
                    const float* __restrict__ u,
                    float* __restrict__ out,
                    int V)
{
    const int row = blockIdx.x;
    const size_t row_off = (size_t)row * (size_t)V;
    const float4* __restrict__ lg4 = (const float4*)(logits + row_off);
    const float4* __restrict__ uu4 = (const float4*)(u + row_off);
    const int V4 = V >> 2;   // V = 128256, divisible by 4

    const float t      = temps[row];
    const float t_safe = fmaxf(t, 1e-6f);

    const float U_LO = 1e-10f;
    const float U_HI = (float)(1.0 - 1e-7);   // match XLA: double const -> f32

    const float NEG_INF = __int_as_float(0xff800000);
    float gbv = NEG_INF; int gbi = 0;   // greedy argmax (nan_to_num logits)
    float sbv = NEG_INF; int sbi = 0;   // sampled argmax (scaled + gumbel)

    for (int i = threadIdx.x; i < V4; i += NTHREADS) {
        const float4 L = lg4[i];
        const float4 U = uu4[i];
        const int base = i << 2;
        #pragma unroll
        for (int c = 0; c < 4; c++) {
            float x  = nan_to_num_f((&L.x)[c]);
            float uc = fminf(fmaxf((&U.x)[c], U_LO), U_HI);
            // gumbel = -log(-log(uc)); logf == libdevice __nv_logf == XLA's log
            float g  = -logf(-logf(uc));
            // IEEE division + add, matching XLA op-for-op (no fma contraction possible)
            float s  = __fadd_rn(__fdiv_rn(x, t_safe), g);
            const int idx = base + c;
            if (x > gbv) { gbv = x; gbi = idx; }  // strict >: first max wins in-thread
            if (s > sbv) { sbv = s; sbi = idx; }
        }
    }

    // ---- block reduction: max with lower-index tie-break (jnp.argmax) ----
    const unsigned FULL = 0xffffffffu;
    #pragma unroll
    for (int off = 16; off > 0; off >>= 1) {
        float ov = __shfl_down_sync(FULL, gbv, off);
        int   oi = __shfl_down_sync(FULL, gbi, off);
        if (ov > gbv || (ov == gbv && oi < gbi)) { gbv = ov; gbi = oi; }
        ov = __shfl_down_sync(FULL, sbv, off);
        oi = __shfl_down_sync(FULL, sbi, off);
        if (ov > sbv || (ov == sbv && oi < sbi)) { sbv = ov; sbi = oi; }
    }

    __shared__ float sh_gv[32], sh_sv[32];
    __shared__ int   sh_gi[32], sh_si[32];
    const int wid = threadIdx.x >> 5;
    const int lid = threadIdx.x & 31;
    if (lid == 0) {
        sh_gv[wid] = gbv; sh_gi[wid] = gbi;
        sh_sv[wid] = sbv; sh_si[wid] = sbi;
    }
    __syncthreads();

    if (wid == 0) {
        gbv = sh_gv[lid]; gbi = sh_gi[lid];
        sbv = sh_sv[lid]; sbi = sh_si[lid];
        #pragma unroll
        for (int off = 16; off > 0; off >>= 1) {
            float ov = __shfl_down_sync(FULL, gbv, off);
            int   oi = __shfl_down_sync(FULL, gbi, off);
            if (ov > gbv || (ov == gbv && oi < gbi)) { gbv = ov; gbi = oi; }
            ov = __shfl_down_sync(FULL, sbv, off);
            oi = __shfl_down_sync(FULL, sbi, off);
            if (ov > sbv || (ov == sbv && oi < sbi)) { sbv = ov; sbi = oi; }
        }
        if (lid == 0) {
            const int chosen = (t <= 1e-6f) ? gbi : sbi;
            out[row] = (float)chosen;   // __output__ dtype is float32
        }
    }
}

extern "C" void kernel_launch(void* const* d_in, const int* in_sizes, int n_in,
                              void* d_out, int out_size)
{
    const float* logits = (const float*)d_in[0];
    const float* temps  = (const float*)d_in[1];
    const float* u      = (const float*)d_in[2];
    float* out = (float*)d_out;

    // Robust shape derivation: temperatures is the small input (B elems)
    int B = in_sizes[1];
    const int V = in_sizes[0] / B;

    sampler_kernel<<<B, NTHREADS>>>(logits, temps, u, out, V);
}